// round 5
// baseline (speedup 1.0000x reference)
#include <cuda_runtime.h>
#include <cstdint>
#include <cstddef>

#define BB 8
#define LL 2048
#define HH 256
#define ROWS 128
#define JT 64
#define NT (LL / JT)
#define PDST 66           // Psd row stride in ull (even -> 16B-aligned pair rows)
#define WST 258

typedef unsigned long long ull;

// -------- scratch (no allocations allowed: __device__ globals) --------
__device__ float g_base[LL];
__device__ float g_st[BB * LL];
__device__ float g_so[BB * LL];
__device__ float g_mult[BB * LL];

// ---------------------------------------------------------------------
// f32x2 helpers (Blackwell packed fp32 pipe)
// ---------------------------------------------------------------------
__device__ __forceinline__ ull pack_dup(float p) {
    ull r;
    asm("mov.b64 %0, {%1, %1};" : "=l"(r) : "f"(p));
    return r;
}
__device__ __forceinline__ void fma2(ull& d, ull a, ull b) {
    asm("fma.rn.f32x2 %0, %1, %2, %0;" : "+l"(d) : "l"(a), "l"(b));
}
__device__ __forceinline__ void mul2(ull& d, ull a) {
    asm("mul.rn.f32x2 %0, %0, %1;" : "+l"(d) : "l"(a));
}
__device__ __forceinline__ void unpack2(ull v, float& lo, float& hi) {
    asm("mov.b64 {%0, %1}, %2;" : "=f"(lo), "=f"(hi) : "l"(v));
}

// ---------------------------------------------------------------------
// Kernel 0: base table + per-token column multiplier
// ---------------------------------------------------------------------
__global__ void k_base_mult(const int* __restrict__ pos) {
    int i = blockIdx.x * blockDim.x + threadIdx.x;
    if (i < LL) {
        g_base[i] = (i == 0) ? 0.5f : (1.0f / log2f(2.0f + (float)i));
    }
    if (i < BB * LL) {
        const unsigned long long mask =
            (1ULL << 19) | (1ULL << 20) | (1ULL << 21) |
            (1ULL << 33) | (1ULL << 34) | (1ULL << 35) |
            (1ULL << 41) | (1ULL << 42) | (1ULL << 43) |
            (1ULL << 44) | (1ULL << 45) | (1ULL << 46);
        int p = pos[i];
        bool op = (p >= 0) && (p < 64) && (((mask >> p) & 1ULL) != 0ULL);
        g_mult[i] = op ? 8.0f : 1.0f;
    }
}

// ---------------------------------------------------------------------
// Kernel 1: fused per-token transforms (y=0 -> st, y=1 -> so)
// ---------------------------------------------------------------------
__global__ __launch_bounds__(256)
void k_transform2(const float* __restrict__ text, const float* __restrict__ opinion,
                  const float* __restrict__ Wt, const float* __restrict__ bt,
                  const float* __restrict__ Wo, const float* __restrict__ wa,
                  const float* __restrict__ ba) {
    __shared__ float Ws[32 * WST];
    __shared__ float Xs[32 * 36];
    __shared__ float bias_s[256];
    __shared__ float wa_s[256];

    int which = blockIdx.y;
    const float* X = which ? opinion : text;
    const float* W = which ? Wo : Wt;
    const float* wav = which ? (wa + HH) : wa;

    int tid = threadIdx.x;
    int tx = tid & 31, ty = tid >> 5;
    int tok0 = blockIdx.x * 32;

    bias_s[tid] = which ? 0.0f : bt[tid];
    wa_s[tid] = wav[tid];

    ull acc2[4][4];
#pragma unroll
    for (int q = 0; q < 4; ++q)
#pragma unroll
        for (int m = 0; m < 4; ++m) acc2[q][m] = 0ULL;

    int kkl = tid & 31;
    int hb = tid >> 5;

    for (int k0 = 0; k0 < 256; k0 += 32) {
        __syncthreads();
#pragma unroll
        for (int r = 0; r < 32; ++r) {
            int h = hb + r * 8;
            Ws[kkl * WST + h] = W[h * 256 + k0 + kkl];
        }
#pragma unroll
        for (int r = 0; r < 4; ++r) {
            int idx = r * 256 + tid;
            int tok = idx >> 5, kk = idx & 31;
            Xs[tok * 36 + kk] = X[(size_t)(tok0 + tok) * 256 + k0 + kk];
        }
        __syncthreads();
#pragma unroll 8
        for (int kk = 0; kk < 32; ++kk) {
            ull wv[4];
#pragma unroll
            for (int m = 0; m < 4; ++m)
                wv[m] = *(const ull*)(Ws + kk * WST + tx * 2 + 64 * m);
            ull xd[4];
#pragma unroll
            for (int q = 0; q < 4; ++q)
                xd[q] = pack_dup(Xs[(ty * 4 + q) * 36 + kk]);
#pragma unroll
            for (int q = 0; q < 4; ++q)
#pragma unroll
                for (int m = 0; m < 4; ++m)
                    fma2(acc2[q][m], xd[q], wv[m]);
        }
    }

    float e = which ? ba[0] : 0.0f;
    float part[4];
#pragma unroll
    for (int q = 0; q < 4; ++q) {
        float s = 0.0f;
#pragma unroll
        for (int m = 0; m < 4; ++m) {
            int h = tx * 2 + 64 * m;
            float a0, a1;
            unpack2(acc2[q][m], a0, a1);
            s += tanhf(a0 + bias_s[h]) * wa_s[h];
            s += tanhf(a1 + bias_s[h + 1]) * wa_s[h + 1];
        }
        part[q] = s;
    }
#pragma unroll
    for (int off = 16; off; off >>= 1) {
#pragma unroll
        for (int q = 0; q < 4; ++q)
            part[q] += __shfl_xor_sync(0xffffffffu, part[q], off);
    }
    if (tx == 0) {
        float* outp = which ? g_so : g_st;
#pragma unroll
        for (int q = 0; q < 4; ++q)
            outp[tok0 + ty * 4 + q] = part[q] + e;
    }
}

// ---------------------------------------------------------------------
// Kernel 2: flash attention. 512 threads, 128 rows/CTA, JT=64 double-buffered.
// Thread tile 8 rows x 8 feats (two 16B groups, conflict-free LDS).
// P stored pre-duplicated ({p,p} ull) -> PV loop is pure fma2 + LDS.
// ---------------------------------------------------------------------
__device__ __forceinline__ void cp16(float* s, const float* g) {
    unsigned sa = (unsigned)__cvta_generic_to_shared(s);
    asm volatile("cp.async.cg.shared.global [%0], [%1], 16;\n" ::"r"(sa), "l"(g));
}

__global__ __launch_bounds__(512, 1)
void k_attn(const float* __restrict__ V, float* __restrict__ out) {
    extern __shared__ float sm[];
    float* Vs = sm;                               // 2 * 64 * 256 = 32768 floats
    ull* Psd = (ull*)(Vs + 2 * JT * HH);          // 128 * 66 ull
    float* base_s = (float*)(Psd + ROWS * PDST);  // 2048
    float* M_s = base_s + LL;                     // 128
    float* S_s = M_s + ROWS;                      // 128
    float* F_s = S_s + ROWS;                      // 128

    int tid = threadIdx.x;
    int tx = tid & 31, ty = tid >> 5;             // ty 0..15
    int b = blockIdx.x >> 4;
    int row0 = (blockIdx.x & 15) * ROWS;

    const float* Vg = V + (size_t)b * LL * HH;
    const float* sog = g_so + b * LL;
    const float* mug = g_mult + b * LL;

    for (int i = tid; i < LL; i += 512) base_s[i] = g_base[i];
    if (tid < ROWS) { M_s[tid] = -1e30f; S_s[tid] = 0.0f; }

    // prefetch tile 0 (64 j x 256 feat = 64KB) into buffer 0
#pragma unroll
    for (int r = 0; r < 8; ++r) {
        int c = r * 512 + tid;
        cp16(Vs + c * 4, Vg + c * 4);
    }
    asm volatile("cp.async.commit_group;\n");

    // score mapping: 4 threads per row, 16 consecutive j each
    int sr = tid >> 2;              // 0..127
    int sjo = (tid & 3) * 16;
    float sti = g_st[b * LL + row0 + sr];
    int gi = row0 + sr;

    ull acc[8][4];
#pragma unroll
    for (int r = 0; r < 8; ++r)
#pragma unroll
        for (int m = 0; m < 4; ++m) acc[r][m] = 0ULL;

    __syncthreads();

    for (int t = 0; t < NT; ++t) {
        if (t) __syncthreads();     // protect Psd/F_s vs previous PV readers
        int j0 = t * JT;

        // ---- score phase: 16 scores per thread (so/mu streamed) ----
        float s[16];
        float lm = -1e30f;
#pragma unroll
        for (int w = 0; w < 4; ++w) {
            float4 so4 = *(const float4*)(sog + j0 + sjo + 4 * w);
            float4 mu4 = *(const float4*)(mug + j0 + sjo + 4 * w);
            float sv[4] = {so4.x, so4.y, so4.z, so4.w};
            float mv[4] = {mu4.x, mu4.y, mu4.z, mu4.w};
#pragma unroll
            for (int u = 0; u < 4; ++u) {
                int j = j0 + sjo + 4 * w + u;
                int d = gi - j; d = (d < 0) ? -d : d;
                float sc = (sti + sv[u]) * base_s[d] * mv[u];
                s[4 * w + u] = sc;
                lm = fmaxf(lm, sc);
            }
        }
        lm = fmaxf(lm, __shfl_xor_sync(0xffffffffu, lm, 1));
        lm = fmaxf(lm, __shfl_xor_sync(0xffffffffu, lm, 2));
        float Mold = M_s[sr];
        float Mn = fmaxf(Mold, lm);
        float ls = 0.0f;
#pragma unroll
        for (int u = 0; u < 16; ++u) {
            float p = __expf(s[u] - Mn);
            Psd[sr * PDST + sjo + u] = pack_dup(p);
            ls += p;
        }
        ls += __shfl_xor_sync(0xffffffffu, ls, 1);
        ls += __shfl_xor_sync(0xffffffffu, ls, 2);
        if ((tid & 3) == 0) {
            float f = __expf(Mold - Mn);
            F_s[sr] = f;
            M_s[sr] = Mn;
            S_s[sr] = S_s[sr] * f + ls;
        }

        // ---- prefetch next V tile ----
        if (t + 1 < NT) {
            float* Vn = Vs + ((t + 1) & 1) * JT * HH;
            const float* gs = Vg + (size_t)(j0 + JT) * HH;
#pragma unroll
            for (int r = 0; r < 8; ++r) {
                int c = r * 512 + tid;
                cp16(Vn + c * 4, gs + c * 4);
            }
            asm volatile("cp.async.commit_group;\n");
            asm volatile("cp.async.wait_group 1;\n");
        } else {
            asm volatile("cp.async.wait_group 0;\n");
        }
        __syncthreads();  // V tile + Psd + F_s visible

        // ---- PV phase: 8 rows x (4 + 4) feats, conflict-free V loads ----
        const ulonglong2* V2 = (const ulonglong2*)(Vs + (t & 1) * JT * HH);
        const ulonglong2* Pdd = (const ulonglong2*)Psd;
#pragma unroll
        for (int r = 0; r < 8; ++r) {
            ull fd = pack_dup(F_s[ty * 8 + r]);
#pragma unroll
            for (int m = 0; m < 4; ++m) mul2(acc[r][m], fd);
        }
        int prow = ty * 8 * (PDST / 2);   // row stride in ulonglong2 = 33
#pragma unroll 2
        for (int j2 = 0; j2 < JT / 2; ++j2) {
            // group A: floats [4tx,4tx+4) ; group B: floats [128+4tx,128+4tx+4)
            ulonglong2 u00 = V2[(size_t)(2 * j2) * 64 + tx];
            ulonglong2 u01 = V2[(size_t)(2 * j2) * 64 + 32 + tx];
            ulonglong2 u10 = V2[(size_t)(2 * j2 + 1) * 64 + tx];
            ulonglong2 u11 = V2[(size_t)(2 * j2 + 1) * 64 + 32 + tx];
#pragma unroll
            for (int r = 0; r < 8; ++r) {
                ulonglong2 pp = Pdd[prow + r * (PDST / 2) + j2];
                fma2(acc[r][0], pp.x, u00.x);
                fma2(acc[r][1], pp.x, u00.y);
                fma2(acc[r][2], pp.x, u01.x);
                fma2(acc[r][3], pp.x, u01.y);
                fma2(acc[r][0], pp.y, u10.x);
                fma2(acc[r][1], pp.y, u10.y);
                fma2(acc[r][2], pp.y, u11.x);
                fma2(acc[r][3], pp.y, u11.y);
            }
        }
    }

    // ---- epilogue: normalize and store (two float4 groups per row) ----
    float* Ob = out + ((size_t)b * LL + row0) * HH;
#pragma unroll
    for (int r = 0; r < 8; ++r) {
        int row = ty * 8 + r;
        float inv = 1.0f / S_s[row];
        float4 o0, o1;
        unpack2(acc[r][0], o0.x, o0.y);
        unpack2(acc[r][1], o0.z, o0.w);
        unpack2(acc[r][2], o1.x, o1.y);
        unpack2(acc[r][3], o1.z, o1.w);
        o0.x *= inv; o0.y *= inv; o0.z *= inv; o0.w *= inv;
        o1.x *= inv; o1.y *= inv; o1.z *= inv; o1.w *= inv;
        *(float4*)(Ob + (size_t)row * HH + tx * 4) = o0;
        *(float4*)(Ob + (size_t)row * HH + 128 + tx * 4) = o1;
    }
}

// ---------------------------------------------------------------------
extern "C" void kernel_launch(void* const* d_in, const int* in_sizes, int n_in,
                              void* d_out, int out_size) {
    const float* opinion = (const float*)d_in[0];
    const float* text    = (const float*)d_in[1];
    const int*   pos     = (const int*)d_in[2];
    const float* Wt      = (const float*)d_in[3];
    const float* bt      = (const float*)d_in[4];
    const float* Wo      = (const float*)d_in[5];
    const float* wa      = (const float*)d_in[6];
    const float* ba      = (const float*)d_in[7];
    float* out = (float*)d_out;

    const int attn_smem =
        (2 * JT * HH) * 4 + (ROWS * PDST) * 8 + (LL + 3 * ROWS) * 4;
    cudaFuncSetAttribute(k_attn, cudaFuncAttributeMaxDynamicSharedMemorySize,
                         attn_smem);

    k_base_mult<<<(BB * LL + 255) / 256, 256>>>(pos);
    k_transform2<<<dim3(BB * LL / 32, 2), 256>>>(text, opinion, Wt, bt, Wo, wa, ba);
    k_attn<<<BB * (LL / ROWS), 512, attn_smem>>>(opinion, out);
}